// round 6
// baseline (speedup 1.0000x reference)
#include <cuda_runtime.h>
#include <cuda_bf16.h>

// Fused blocked affine-scan RK4 integrator, v5 (single kernel, grid barrier).
// x_{t+1} = A x_t + B u_t exactly. L=16, 6250 chunks, 98 blocks x 64 thr:
//   phase1: smem tile of u (coalesced, loaded ONCE), 16-step zero-IC scan.
//   grid barrier (sense-reversing atomic; all blocks co-resident).
//   phase2: block 0 hierarchical boundary scan (64 lanes, q~98).
//   grid barrier.
//   phase3: replay from known start states on the SAME smem tile, store.

#define L_CHUNK 16
#define CPB 64
#define F4_PER_CHUNK (L_CHUNK / 2)
#define MAX_CHUNKS 8192

__device__ float4 g_cd[MAX_CHUNKS];        // per-chunk drive vectors
__device__ float4 g_cx[MAX_CHUNKS + 1];    // chunk start states
__device__ volatile unsigned g_sense = 0;  // monotonically increasing epoch
__device__ unsigned g_count = 0;           // arrival counter (self-resetting)

// ---------------------------------------------------------------------------
// Grid barrier: sense-reversing, safe across graph replays (sense only grows)
// ---------------------------------------------------------------------------
__device__ __forceinline__ void grid_barrier(int nblocks) {
    __threadfence();           // make this thread's prior writes device-visible
    __syncthreads();
    if (threadIdx.x == 0) {
        unsigned s = g_sense;
        unsigned my = atomicAdd(&g_count, 1);
        if (my == (unsigned)nblocks - 1) {
            g_count = 0;
            __threadfence();
            g_sense = s + 1;
        } else {
            while (g_sense == s) { }
        }
    }
    __syncthreads();
}

// ---------------------------------------------------------------------------
// fp32 RK4 step mirroring the reference arithmetic (basis probing only)
// ---------------------------------------------------------------------------
struct FSys { float Cm[4], Km[4], Md[2], dt; };

__device__ __forceinline__ FSys mksys(const float* M, const float* C,
                                      const float* K, const float* dtp) {
    FSys m;
    m.Md[0] = M[0]; m.Md[1] = M[1];
    float C0 = C[0], C1 = C[1], C2 = C[2];
    m.Cm[0] = C0 + C1; m.Cm[1] = -C1; m.Cm[2] = -C1; m.Cm[3] = C2 + C1;
    float K0 = K[0], K1 = K[1], K2 = K[2];
    m.Km[0] = K0 + K1; m.Km[1] = -K1; m.Km[2] = -K1; m.Km[3] = K2 + K1;
    m.dt = dtp[0];
    return m;
}

__device__ void fstep(const FSys& m, float s[4], float u0, float u1) {
    float dt = m.dt;
    float y0 = s[0], y1 = s[1], v0 = s[2], v1 = s[3];
#define ACC(z0, z1, w0, w1, a0, a1)                                             \
    a0 = (u0 - (m.Cm[0]*(w0) + m.Cm[1]*(w1)) - (m.Km[0]*(z0) + m.Km[1]*(z1))) / m.Md[0]; \
    a1 = (u1 - (m.Cm[2]*(w0) + m.Cm[3]*(w1)) - (m.Km[2]*(z0) + m.Km[3]*(z1))) / m.Md[1];
    float k1a, k1b; ACC(y0, y1, v0, v1, k1a, k1b);
    float y2a = y0 + v0*dt*0.5f, y2b = y1 + v1*dt*0.5f;
    float v2a = v0 + k1a*dt*0.5f, v2b = v1 + k1b*dt*0.5f;
    float k2a, k2b; ACC(y2a, y2b, v2a, v2b, k2a, k2b);
    float y3a = y0 + v2a*dt*0.5f, y3b = y1 + v2b*dt*0.5f;
    float v3a = v0 + k2a*dt*0.5f, v3b = v1 + k2b*dt*0.5f;
    float k3a, k3b; ACC(y3a, y3b, v3a, v3b, k3a, k3b);
    float y4a = y0 + v3a*dt, y4b = y1 + v3b*dt;
    float v4a = v0 + k3a*dt, v4b = v1 + k3b*dt;
    float k4a, k4b; ACC(y4a, y4b, v4a, v4b, k4a, k4b);
    (void)y2a; (void)y2b; (void)y3a; (void)y3b; (void)y4a; (void)y4b;
    s[0] = y0 + dt/6.f * (v0 + 2.f*v2a + 2.f*v3a + v4a);
    s[1] = y1 + dt/6.f * (v1 + 2.f*v2b + 2.f*v3b + v4b);
    s[2] = v0 + dt/6.f * (k1a + 2.f*k2a + 2.f*k3a + k4a);
    s[3] = v1 + dt/6.f * (k1b + 2.f*k2b + 2.f*k3b + k4b);
#undef ACC
}

__device__ __forceinline__ void probe_AB(float* sA, float* sB,
                                         const float* M, const float* C,
                                         const float* K, const float* dtp, int t) {
    if (t < 4) {
        FSys m = mksys(M, C, K, dtp);
        float s[4] = {0.f, 0.f, 0.f, 0.f}; s[t] = 1.f;
        fstep(m, s, 0.f, 0.f);
        sA[0*4 + t] = s[0]; sA[1*4 + t] = s[1]; sA[2*4 + t] = s[2]; sA[3*4 + t] = s[3];
    } else if (t < 6) {
        FSys m = mksys(M, C, K, dtp);
        int j = t - 4;
        float s[4] = {0.f, 0.f, 0.f, 0.f};
        fstep(m, s, j == 0 ? 1.f : 0.f, j == 1 ? 1.f : 0.f);
        sB[0*2 + j] = s[0]; sB[1*2 + j] = s[1]; sB[2*2 + j] = s[2]; sB[3*2 + j] = s[3];
    }
}

// ---------------------------------------------------------------------------
// x <- Am x + d  (tree-reduced, 12-cycle critical path)
// ---------------------------------------------------------------------------
#define MATVEC4(Am, d0, d1, d2, d3, x0_, x1_, x2_, x3_)                        \
    do {                                                                       \
        float n0 = fmaf((Am)[0],  (x0_), (Am)[1]  * (x1_)) +                   \
                   fmaf((Am)[2],  (x2_), fmaf((Am)[3],  (x3_), (d0)));         \
        float n1 = fmaf((Am)[4],  (x0_), (Am)[5]  * (x1_)) +                   \
                   fmaf((Am)[6],  (x2_), fmaf((Am)[7],  (x3_), (d1)));         \
        float n2 = fmaf((Am)[8],  (x0_), (Am)[9]  * (x1_)) +                   \
                   fmaf((Am)[10], (x2_), fmaf((Am)[11], (x3_), (d2)));         \
        float n3 = fmaf((Am)[12], (x0_), (Am)[13] * (x1_)) +                   \
                   fmaf((Am)[14], (x2_), fmaf((Am)[15], (x3_), (d3)));         \
        (x0_) = n0; (x1_) = n1; (x2_) = n2; (x3_) = n3;                        \
    } while (0)

// Cooperative 4x4 matmul + power (threads 0..15 of warp 0)
__device__ __forceinline__ void coop_mm(float* R, const float* Pm, const float* Qm, int t) {
    if (t < 16) {
        int i = t >> 2, j = t & 3;
        R[t] = fmaf(Pm[i*4+0], Qm[0*4+j],
               fmaf(Pm[i*4+1], Qm[1*4+j],
               fmaf(Pm[i*4+2], Qm[2*4+j],
                    Pm[i*4+3] * Qm[3*4+j])));
    }
    __syncwarp();
}

__device__ void coop_pow(float* dst, const float* base, int e,
                         float* sP, float* sQ, float* sR, int t) {
    if (t < 16) {
        sP[t] = (t == 0 || t == 5 || t == 10 || t == 15) ? 1.f : 0.f;
        sQ[t] = base[t];
    }
    __syncwarp();
    while (e) {
        if (e & 1) {
            coop_mm(sR, sP, sQ, t);
            if (t < 16) sP[t] = sR[t];
            __syncwarp();
        }
        e >>= 1;
        if (e) {
            coop_mm(sR, sQ, sQ, t);
            if (t < 16) sQ[t] = sR[t];
            __syncwarp();
        }
    }
    if (t < 16) dst[t] = sP[t];
    __syncwarp();
}

// ---------------------------------------------------------------------------
// Fused kernel
// ---------------------------------------------------------------------------
__global__ void __launch_bounds__(CPB, 1)
fused_kernel(const float4* __restrict__ u4, float4* __restrict__ out4,
             const float* __restrict__ M, const float* __restrict__ C,
             const float* __restrict__ K, const float* __restrict__ x0in,
             const float* __restrict__ dtp,
             int NC, int P, int nf4, int q, int nact, int nblocks) {
    __shared__ float sA[16], sB[8];
    __shared__ float sM[16], sMq[16], sMr[16], sP_[16], sQ_[16], sR_[16];
    __shared__ float4 s_e[CPB], s_x[CPB];
    __shared__ float2 s_u[L_CHUNK][CPB + 2];

    int tid = threadIdx.x;
    int c0 = blockIdx.x * CPB;
    int c = c0 + tid;

    probe_AB(sA, sB, M, C, K, dtp, tid);

    // ---- stage u tile: 512 contiguous float4 -> transposed smem -------------
#pragma unroll
    for (int k = 0; k < 8; k++) {
        int idx = tid + CPB * k;
        int g4 = c0 * F4_PER_CHUNK + idx;
        float4 qv = (g4 < nf4) ? u4[g4] : make_float4(0.f, 0.f, 0.f, 0.f);
        int cc = idx >> 3, j = idx & 7;
        s_u[2*j][cc]     = make_float2(qv.x, qv.y);
        s_u[2*j + 1][cc] = make_float2(qv.z, qv.w);
    }
    __syncthreads();

    float A[16], B[8];
#pragma unroll
    for (int i = 0; i < 16; i++) A[i] = sA[i];
#pragma unroll
    for (int i = 0; i < 8; i++) B[i] = sB[i];

    // ---- phase1: zero-IC drive vector ---------------------------------------
    {
        float x0 = 0.f, x1 = 0.f, x2 = 0.f, x3 = 0.f;
#pragma unroll
        for (int i = 0; i < L_CHUNK; i++) {
            float2 uu = s_u[i][tid];
            float w0 = fmaf(B[0], uu.x, B[1] * uu.y);
            float w1 = fmaf(B[2], uu.x, B[3] * uu.y);
            float w2 = fmaf(B[4], uu.x, B[5] * uu.y);
            float w3 = fmaf(B[6], uu.x, B[7] * uu.y);
            MATVEC4(A, w0, w1, w2, w3, x0, x1, x2, x3);
        }
        if (c < P) g_cd[c] = make_float4(x0, x1, x2, x3);
    }

    grid_barrier(nblocks);

    // ---- phase2: block 0 hierarchical boundary scan --------------------------
    if (blockIdx.x == 0) {
        if (tid < 32) {
            coop_pow(sM,  sA, L_CHUNK, sP_, sQ_, sR_, tid);  // M = A^L
            coop_pow(sMq, sM, q,       sP_, sQ_, sR_, tid);  // M^q
        }
        __syncthreads();

        float Mm[16];
#pragma unroll
        for (int i = 0; i < 16; i++) Mm[i] = sM[i];

        int lo = tid * q;
        int hi = lo + q; if (hi > P) hi = P;

        float e0 = 0.f, e1 = 0.f, e2 = 0.f, e3 = 0.f;
#pragma unroll 4
        for (int j = lo; j < hi; j++) {
            float4 d = __ldcg(&g_cd[j]);
            MATVEC4(Mm, d.x, d.y, d.z, d.w, e0, e1, e2, e3);
        }
        s_e[tid] = make_float4(e0, e1, e2, e3);
        __syncthreads();

        if (tid == 0) {
            float Mq[16];
#pragma unroll
            for (int i = 0; i < 16; i++) Mq[i] = sMq[i];
            // x0 layout [y1,v1,y2,v2] -> state [y1,y2,v1,v2]
            float x0 = x0in[0], x1 = x0in[2], x2 = x0in[1], x3 = x0in[3];
            g_cx[0] = make_float4(x0, x1, x2, x3);
            // combine: every partial except possibly the last covers exactly q
            // chunks; the last partial is never needed further, so using Mq for
            // all transitions up to nact-1 is exact (we stop before applying it).
            for (int tt = 0; tt < nact; tt++) {
                s_x[tt] = make_float4(x0, x1, x2, x3);
                if (tt < nact - 1) {
                    float4 d = s_e[tt];
                    MATVEC4(Mq, d.x, d.y, d.z, d.w, x0, x1, x2, x3);
                }
            }
        }
        __syncthreads();

        if (lo < P) {
            float4 xx = s_x[tid];
            float x0 = xx.x, x1 = xx.y, x2 = xx.z, x3 = xx.w;
#pragma unroll 4
            for (int j = lo; j < hi; j++) {
                float4 d = __ldcg(&g_cd[j]);
                MATVEC4(Mm, d.x, d.y, d.z, d.w, x0, x1, x2, x3);
                g_cx[j + 1] = make_float4(x0, x1, x2, x3);
            }
        }
    }

    grid_barrier(nblocks);

    // ---- phase3: replay from known start state on the resident tile ---------
    {
        float x0 = 0.f, x1 = 0.f, x2 = 0.f, x3 = 0.f;
        if (c < NC) {
            float4 xx = __ldcg(&g_cx[c]);
            x0 = xx.x; x1 = xx.y; x2 = xx.z; x3 = xx.w;
        }
#pragma unroll
        for (int i = 0; i < L_CHUNK; i++) {
            float2 uu = s_u[i][tid];
            float w0 = fmaf(B[0], uu.x, B[1] * uu.y);
            float w1 = fmaf(B[2], uu.x, B[3] * uu.y);
            float w2 = fmaf(B[4], uu.x, B[5] * uu.y);
            float w3 = fmaf(B[6], uu.x, B[7] * uu.y);
            MATVEC4(A, w0, w1, w2, w3, x0, x1, x2, x3);
            s_u[i][tid] = make_float2(x0, x1);   // positions after the step
        }
    }
    __syncthreads();

    // ---- coalesced transposed store ------------------------------------------
#pragma unroll
    for (int k = 0; k < 8; k++) {
        int idx = tid + CPB * k;
        int g4 = c0 * F4_PER_CHUNK + idx;
        if (g4 < nf4) {
            int cc = idx >> 3, j = idx & 7;
            float2 a = s_u[2*j][cc];
            float2 b = s_u[2*j + 1][cc];
            out4[g4] = make_float4(a.x, a.y, b.x, b.y);
        }
    }
}

// ---------------------------------------------------------------------------
// Launch
// ---------------------------------------------------------------------------
extern "C" void kernel_launch(void* const* d_in, const int* in_sizes, int n_in,
                              void* d_out, int out_size) {
    const float* u  = (const float*)d_in[0];
    const float* M  = (const float*)d_in[1];
    const float* C  = (const float*)d_in[2];
    const float* K  = (const float*)d_in[3];
    const float* x0 = (const float*)d_in[4];
    const float* dt = (const float*)d_in[5];

    int T  = in_sizes[0] / 2;
    int NC = (T + L_CHUNK - 1) / L_CHUNK;
    int P  = NC - 1;
    int q  = (P + CPB - 1) / CPB; if (q < 1) q = 1;
    int nact = (P > 0) ? (P + q - 1) / q : 1;
    int nf4 = (2 * T) / 4;
    int nb  = (NC + CPB - 1) / CPB;   // 98 blocks for T=100000 — all co-resident

    fused_kernel<<<nb, CPB>>>((const float4*)u, (float4*)d_out,
                              M, C, K, x0, dt, NC, P, nf4, q, nact, nb);
}

// round 9
// speedup vs baseline: 4.2353x; 4.2353x over previous
#include <cuda_runtime.h>
#include <cuda_bf16.h>

// Fused blocked affine-scan RK4 integrator, v6.2 (fixes the no-op lane ladder:
// MATVEC4(Am, d, x) computes x <- Am*x + d; ladder must pass v as x, 0 as d).
// x_{t+1} = A x_t + B u_t exactly. L=16, 6250 chunks, 98 blocks x 64 thr.
//   per lane : 16-step chunk scan (smem tile, loaded once)
//   per warp : Kogge-Stone affine scan (shuffles, M^(2^k) precomputed)
//   per block: warp totals -> block total -> g_bt
//   barrier  : block 0 scans 98 block totals (smem-staged, 1 latency)
//   barrier  : lanes rebuild start states via 5-step matrix ladder, replay.

#define L_CHUNK 16
#define CPB 64
#define F4_PER_CHUNK (L_CHUNK / 2)
#define MAX_BLOCKS 256

__device__ float4 g_bt[MAX_BLOCKS];        // per-block total drive
__device__ float4 g_bs[MAX_BLOCKS];        // per-block start state
__device__ volatile unsigned g_sense = 0;  // monotonically increasing epoch
__device__ unsigned g_count = 0;           // arrival counter (self-resetting)

// ---------------------------------------------------------------------------
// Grid barrier: sense-reversing with nanosleep backoff
// ---------------------------------------------------------------------------
__device__ __forceinline__ void grid_barrier(int nblocks) {
    __threadfence();
    __syncthreads();
    if (threadIdx.x == 0) {
        unsigned s = g_sense;
        unsigned my = atomicAdd(&g_count, 1);
        if (my == (unsigned)nblocks - 1) {
            g_count = 0;
            __threadfence();
            g_sense = s + 1;
        } else {
            while (g_sense == s) { __nanosleep(32); }
        }
    }
    __syncthreads();
}

// ---------------------------------------------------------------------------
// fp32 RK4 step mirroring the reference arithmetic (basis probing only)
// ---------------------------------------------------------------------------
struct FSys { float Cm[4], Km[4], Md[2], dt; };

__device__ __forceinline__ FSys mksys(const float* M, const float* C,
                                      const float* K, const float* dtp) {
    FSys m;
    m.Md[0] = M[0]; m.Md[1] = M[1];
    float C0 = C[0], C1 = C[1], C2 = C[2];
    m.Cm[0] = C0 + C1; m.Cm[1] = -C1; m.Cm[2] = -C1; m.Cm[3] = C2 + C1;
    float K0 = K[0], K1 = K[1], K2 = K[2];
    m.Km[0] = K0 + K1; m.Km[1] = -K1; m.Km[2] = -K1; m.Km[3] = K2 + K1;
    m.dt = dtp[0];
    return m;
}

__device__ void fstep(const FSys& m, float s[4], float u0, float u1) {
    float dt = m.dt;
    float y0 = s[0], y1 = s[1], v0 = s[2], v1 = s[3];
#define ACC(z0, z1, w0, w1, a0, a1)                                             \
    a0 = (u0 - (m.Cm[0]*(w0) + m.Cm[1]*(w1)) - (m.Km[0]*(z0) + m.Km[1]*(z1))) / m.Md[0]; \
    a1 = (u1 - (m.Cm[2]*(w0) + m.Cm[3]*(w1)) - (m.Km[2]*(z0) + m.Km[3]*(z1))) / m.Md[1];
    float k1a, k1b; ACC(y0, y1, v0, v1, k1a, k1b);
    float y2a = y0 + v0*dt*0.5f, y2b = y1 + v1*dt*0.5f;
    float v2a = v0 + k1a*dt*0.5f, v2b = v1 + k1b*dt*0.5f;
    float k2a, k2b; ACC(y2a, y2b, v2a, v2b, k2a, k2b);
    float y3a = y0 + v2a*dt*0.5f, y3b = y1 + v2b*dt*0.5f;
    float v3a = v0 + k2a*dt*0.5f, v3b = v1 + k2b*dt*0.5f;
    float k3a, k3b; ACC(y3a, y3b, v3a, v3b, k3a, k3b);
    float y4a = y0 + v3a*dt, y4b = y1 + v3b*dt;
    float v4a = v0 + k3a*dt, v4b = v1 + k3b*dt;
    float k4a, k4b; ACC(y4a, y4b, v4a, v4b, k4a, k4b);
    (void)y2a; (void)y2b; (void)y3a; (void)y3b; (void)y4a; (void)y4b;
    s[0] = y0 + dt/6.f * (v0 + 2.f*v2a + 2.f*v3a + v4a);
    s[1] = y1 + dt/6.f * (v1 + 2.f*v2b + 2.f*v3b + v4b);
    s[2] = v0 + dt/6.f * (k1a + 2.f*k2a + 2.f*k3a + k4a);
    s[3] = v1 + dt/6.f * (k1b + 2.f*k2b + 2.f*k3b + k4b);
#undef ACC
}

__device__ __forceinline__ void probe_AB(float* sA, float* sB,
                                         const float* M, const float* C,
                                         const float* K, const float* dtp, int t) {
    if (t < 4) {
        FSys m = mksys(M, C, K, dtp);
        float s[4] = {0.f, 0.f, 0.f, 0.f}; s[t] = 1.f;
        fstep(m, s, 0.f, 0.f);
        sA[0*4 + t] = s[0]; sA[1*4 + t] = s[1]; sA[2*4 + t] = s[2]; sA[3*4 + t] = s[3];
    } else if (t < 6) {
        FSys m = mksys(M, C, K, dtp);
        int j = t - 4;
        float s[4] = {0.f, 0.f, 0.f, 0.f};
        fstep(m, s, j == 0 ? 1.f : 0.f, j == 1 ? 1.f : 0.f);
        sB[0*2 + j] = s[0]; sB[1*2 + j] = s[1]; sB[2*2 + j] = s[2]; sB[3*2 + j] = s[3];
    }
}

// ---------------------------------------------------------------------------
// MATVEC4(Am, d..., x...): x <- Am * x + d   (d is the ADDITIVE term!)
// ---------------------------------------------------------------------------
#define MATVEC4(Am, d0, d1, d2, d3, x0_, x1_, x2_, x3_)                        \
    do {                                                                       \
        float n0 = fmaf((Am)[0],  (x0_), (Am)[1]  * (x1_)) +                   \
                   fmaf((Am)[2],  (x2_), fmaf((Am)[3],  (x3_), (d0)));         \
        float n1 = fmaf((Am)[4],  (x0_), (Am)[5]  * (x1_)) +                   \
                   fmaf((Am)[6],  (x2_), fmaf((Am)[7],  (x3_), (d1)));         \
        float n2 = fmaf((Am)[8],  (x0_), (Am)[9]  * (x1_)) +                   \
                   fmaf((Am)[10], (x2_), fmaf((Am)[11], (x3_), (d2)));         \
        float n3 = fmaf((Am)[12], (x0_), (Am)[13] * (x1_)) +                   \
                   fmaf((Am)[14], (x2_), fmaf((Am)[15], (x3_), (d3)));         \
        (x0_) = n0; (x1_) = n1; (x2_) = n2; (x3_) = n3;                        \
    } while (0)

// v <- Mat * v + b
#define AFFINE_F4(Mat, v, b)                                                   \
    do {                                                                       \
        float t0 = (v).x, t1 = (v).y, t2 = (v).z, t3 = (v).w;                  \
        MATVEC4(Mat, (b).x, (b).y, (b).z, (b).w, t0, t1, t2, t3);              \
        (v).x = t0; (v).y = t1; (v).z = t2; (v).w = t3;                        \
    } while (0)

// Cooperative 4x4 matmul (threads 0..15 of warp 0)
__device__ __forceinline__ void coop_mm(float* R, const float* Pm, const float* Qm, int t) {
    if (t < 16) {
        int i = t >> 2, j = t & 3;
        R[t] = fmaf(Pm[i*4+0], Qm[0*4+j],
               fmaf(Pm[i*4+1], Qm[1*4+j],
               fmaf(Pm[i*4+2], Qm[2*4+j],
                    Pm[i*4+3] * Qm[3*4+j])));
    }
    __syncwarp();
}

// ---------------------------------------------------------------------------
// Fused kernel
// ---------------------------------------------------------------------------
__global__ void __launch_bounds__(CPB, 1)
fused_kernel(const float4* __restrict__ u4, float4* __restrict__ out4,
             const float* __restrict__ M, const float* __restrict__ C,
             const float* __restrict__ K, const float* __restrict__ x0in,
             const float* __restrict__ dtp,
             int nf4, int nblocks) {
    __shared__ float sA[16], sB[8];
    __shared__ float sMp[5][16];      // M^1, M^2, M^4, M^8, M^16   (M = A^16)
    __shared__ float sM32[16];        // M^32
    __shared__ float sM64[16];        // M^64
    __shared__ float sTmp[16];
    __shared__ float4 s_w[2];         // warp totals
    __shared__ float4 s_Sw[2];        // warp start states
    __shared__ float4 s_bt[MAX_BLOCKS];
    __shared__ float2 s_u[L_CHUNK][CPB + 2];

    int tid = threadIdx.x;
    int lane = tid & 31;
    int wrp = tid >> 5;
    int c0 = blockIdx.x * CPB;

    probe_AB(sA, sB, M, C, K, dtp, tid);

    // ---- stage u tile: 512 contiguous float4 -> transposed smem -------------
#pragma unroll
    for (int k = 0; k < 8; k++) {
        int idx = tid + CPB * k;
        int g4 = c0 * F4_PER_CHUNK + idx;
        float4 qv = (g4 < nf4) ? u4[g4] : make_float4(0.f, 0.f, 0.f, 0.f);
        int cc = idx >> 3, j = idx & 7;
        s_u[2*j][cc]     = make_float2(qv.x, qv.y);
        s_u[2*j + 1][cc] = make_float2(qv.z, qv.w);
    }
    __syncthreads();

    // ---- warp 0: build power table M^1..M^64 (M = A^16) ----------------------
    if (wrp == 0) {
        if (lane < 16) sTmp[lane] = sA[lane];
        __syncwarp();
        coop_mm(sMp[0], sTmp, sTmp, lane);               // A^2
        coop_mm(sTmp, sMp[0], sMp[0], lane);             // A^4
        coop_mm(sMp[0], sTmp, sTmp, lane);               // A^8
        coop_mm(sTmp, sMp[0], sMp[0], lane);             // A^16 = M^1
        if (lane < 16) sMp[0][lane] = sTmp[lane];
        __syncwarp();
        coop_mm(sMp[1], sMp[0], sMp[0], lane);           // M^2
        coop_mm(sMp[2], sMp[1], sMp[1], lane);           // M^4
        coop_mm(sMp[3], sMp[2], sMp[2], lane);           // M^8
        coop_mm(sMp[4], sMp[3], sMp[3], lane);           // M^16
        coop_mm(sM32,   sMp[4], sMp[4], lane);           // M^32
        coop_mm(sM64,   sM32,   sM32,   lane);           // M^64
    }

    float A[16], B[8];
#pragma unroll
    for (int i = 0; i < 16; i++) A[i] = sA[i];
#pragma unroll
    for (int i = 0; i < 8; i++) B[i] = sB[i];

    // ---- per-lane chunk drive (zero IC) --------------------------------------
    float d0 = 0.f, d1 = 0.f, d2 = 0.f, d3 = 0.f;
#pragma unroll
    for (int i = 0; i < L_CHUNK; i++) {
        float2 uu = s_u[i][tid];
        float w0 = fmaf(B[0], uu.x, B[1] * uu.y);
        float w1 = fmaf(B[2], uu.x, B[3] * uu.y);
        float w2 = fmaf(B[4], uu.x, B[5] * uu.y);
        float w3 = fmaf(B[6], uu.x, B[7] * uu.y);
        MATVEC4(A, w0, w1, w2, w3, d0, d1, d2, d3);
    }
    __syncthreads();   // power table ready for all warps

    // ---- warp Kogge-Stone inclusive affine scan over lanes -------------------
    // combine: e_new = M^(2^k) * e_prevlane + e
    float4 e = make_float4(d0, d1, d2, d3);
#pragma unroll
    for (int k = 0; k < 5; k++) {
        int off = 1 << k;
        float4 p;
        p.x = __shfl_up_sync(0xffffffffu, e.x, off);
        p.y = __shfl_up_sync(0xffffffffu, e.y, off);
        p.z = __shfl_up_sync(0xffffffffu, e.z, off);
        p.w = __shfl_up_sync(0xffffffffu, e.w, off);
        if (lane >= off) {
            float t0 = p.x, t1 = p.y, t2 = p.z, t3 = p.w;
            MATVEC4(sMp[k], e.x, e.y, e.z, e.w, t0, t1, t2, t3);  // t = M^2^k * p + e
            e = make_float4(t0, t1, t2, t3);
        }
    }
    if (lane == 31) s_w[wrp] = e;      // warp totals (inclusive drive, 32 chunks)
    __syncthreads();

    // ---- block total: E = M^32 * W0 + W1 -> g_bt ------------------------------
    if (tid == 0) {
        float4 bt = s_w[0];
        AFFINE_F4(sM32, bt, s_w[1]);
        g_bt[blockIdx.x] = bt;
    }
    __syncthreads();

    grid_barrier(nblocks);

    // ---- block 0: scan block totals: S_{b+1} = M^64 S_b + E_b ----------------
    if (blockIdx.x == 0) {
        for (int b = tid; b < nblocks; b += CPB)
            s_bt[b] = __ldcg(&g_bt[b]);
        __syncthreads();
        if (tid == 0) {
            // x0 layout [y1,v1,y2,v2] -> state [y1,y2,v1,v2]
            float4 S = make_float4(x0in[0], x0in[2], x0in[1], x0in[3]);
            for (int b = 0; b < nblocks; b++) {
                g_bs[b] = S;
                float4 d = s_bt[b];
                AFFINE_F4(sM64, S, d);
            }
        }
    }

    grid_barrier(nblocks);

    // ---- warp start states: Sw0 = Sb; Sw1 = M^32 * Sb + W0 --------------------
    float4 Sb = __ldcg(&g_bs[blockIdx.x]);
    if (tid == 0) {
        s_Sw[0] = Sb;
        float4 t = Sb;
        AFFINE_F4(sM32, t, s_w[0]);    // t = M^32 * Sb + W0
        s_Sw[1] = t;
    }
    __syncthreads();

    // exclusive prefix of lane drives
    float4 eprev;
    eprev.x = __shfl_up_sync(0xffffffffu, e.x, 1);
    eprev.y = __shfl_up_sync(0xffffffffu, e.y, 1);
    eprev.z = __shfl_up_sync(0xffffffffu, e.z, 1);
    eprev.w = __shfl_up_sync(0xffffffffu, e.w, 1);
    if (lane == 0) eprev = make_float4(0.f, 0.f, 0.f, 0.f);

    // ladder: v <- M^(2^k) * v for each set bit of lane  (FIX: v is the
    // multiplied in/out term; additive term is zero)
    float4 v = s_Sw[wrp];
#pragma unroll
    for (int k = 0; k < 5; k++) {
        if ((lane >> k) & 1) {
            float t0 = v.x, t1 = v.y, t2 = v.z, t3 = v.w;
            MATVEC4(sMp[k], 0.f, 0.f, 0.f, 0.f, t0, t1, t2, t3);  // t = M^2^k * v
            v = make_float4(t0, t1, t2, t3);
        }
    }
    // this lane's chunk start state = M^lane * Sw + eprev
    float x0 = v.x + eprev.x, x1 = v.y + eprev.y;
    float x2 = v.z + eprev.z, x3 = v.w + eprev.w;

    // ---- replay 16 steps, write positions back into the tile -----------------
#pragma unroll
    for (int i = 0; i < L_CHUNK; i++) {
        float2 uu = s_u[i][tid];
        float w0 = fmaf(B[0], uu.x, B[1] * uu.y);
        float w1 = fmaf(B[2], uu.x, B[3] * uu.y);
        float w2 = fmaf(B[4], uu.x, B[5] * uu.y);
        float w3 = fmaf(B[6], uu.x, B[7] * uu.y);
        MATVEC4(A, w0, w1, w2, w3, x0, x1, x2, x3);
        s_u[i][tid] = make_float2(x0, x1);
    }
    __syncthreads();

    // ---- coalesced transposed store -------------------------------------------
#pragma unroll
    for (int k = 0; k < 8; k++) {
        int idx = tid + CPB * k;
        int g4 = c0 * F4_PER_CHUNK + idx;
        if (g4 < nf4) {
            int cc = idx >> 3, j = idx & 7;
            float2 a = s_u[2*j][cc];
            float2 b = s_u[2*j + 1][cc];
            out4[g4] = make_float4(a.x, a.y, b.x, b.y);
        }
    }
}

// ---------------------------------------------------------------------------
// Launch
// ---------------------------------------------------------------------------
extern "C" void kernel_launch(void* const* d_in, const int* in_sizes, int n_in,
                              void* d_out, int out_size) {
    const float* u  = (const float*)d_in[0];
    const float* M  = (const float*)d_in[1];
    const float* C  = (const float*)d_in[2];
    const float* K  = (const float*)d_in[3];
    const float* x0 = (const float*)d_in[4];
    const float* dt = (const float*)d_in[5];

    int T   = in_sizes[0] / 2;
    int NC  = (T + L_CHUNK - 1) / L_CHUNK;
    int nf4 = (2 * T) / 4;
    int nb  = (NC + CPB - 1) / CPB;   // 98 blocks for T=100000 — co-resident

    fused_kernel<<<nb, CPB>>>((const float4*)u, (float4*)d_out,
                              M, C, K, x0, dt, nf4, nb);
}

// round 10
// speedup vs baseline: 4.8600x; 1.1475x over previous
#include <cuda_runtime.h>
#include <cuda_bf16.h>

// Fused blocked affine-scan RK4 integrator, v7 (single grid barrier;
// every block redundantly computes its own prefix over block totals).
// x_{t+1} = A x_t + B u_t exactly. L=16, 6250 chunks, 98 blocks x 64 thr.
//   per lane : 16-step chunk scan (smem tile, loaded once)
//   per warp : Kogge-Stone affine scan (shuffles, M^(2^k) precomputed)
//   per block: warp totals -> block total E_b -> g_bt
//   barrier  : ONE grid barrier
//   each blk : loads all E_* (L2 broadcast), folds own prefix S_b locally,
//              lanes rebuild start states via 5-step matrix ladder, replay.

#define L_CHUNK 16
#define CPB 64
#define F4_PER_CHUNK (L_CHUNK / 2)
#define MAX_BLOCKS 256

__device__ float4 g_bt[MAX_BLOCKS];        // per-block total drive
__device__ volatile unsigned g_sense = 0;  // monotonically increasing epoch
__device__ unsigned g_count = 0;           // arrival counter (self-resetting)

// ---------------------------------------------------------------------------
// Grid barrier: sense-reversing with nanosleep backoff
// ---------------------------------------------------------------------------
__device__ __forceinline__ void grid_barrier(int nblocks) {
    __threadfence();
    __syncthreads();
    if (threadIdx.x == 0) {
        unsigned s = g_sense;
        unsigned my = atomicAdd(&g_count, 1);
        if (my == (unsigned)nblocks - 1) {
            g_count = 0;
            __threadfence();
            g_sense = s + 1;
        } else {
            while (g_sense == s) { __nanosleep(32); }
        }
    }
    __syncthreads();
}

// ---------------------------------------------------------------------------
// fp32 RK4 step mirroring the reference arithmetic (basis probing only)
// ---------------------------------------------------------------------------
struct FSys { float Cm[4], Km[4], Md[2], dt; };

__device__ __forceinline__ FSys mksys(const float* M, const float* C,
                                      const float* K, const float* dtp) {
    FSys m;
    m.Md[0] = M[0]; m.Md[1] = M[1];
    float C0 = C[0], C1 = C[1], C2 = C[2];
    m.Cm[0] = C0 + C1; m.Cm[1] = -C1; m.Cm[2] = -C1; m.Cm[3] = C2 + C1;
    float K0 = K[0], K1 = K[1], K2 = K[2];
    m.Km[0] = K0 + K1; m.Km[1] = -K1; m.Km[2] = -K1; m.Km[3] = K2 + K1;
    m.dt = dtp[0];
    return m;
}

__device__ void fstep(const FSys& m, float s[4], float u0, float u1) {
    float dt = m.dt;
    float y0 = s[0], y1 = s[1], v0 = s[2], v1 = s[3];
#define ACC(z0, z1, w0, w1, a0, a1)                                             \
    a0 = (u0 - (m.Cm[0]*(w0) + m.Cm[1]*(w1)) - (m.Km[0]*(z0) + m.Km[1]*(z1))) / m.Md[0]; \
    a1 = (u1 - (m.Cm[2]*(w0) + m.Cm[3]*(w1)) - (m.Km[2]*(z0) + m.Km[3]*(z1))) / m.Md[1];
    float k1a, k1b; ACC(y0, y1, v0, v1, k1a, k1b);
    float y2a = y0 + v0*dt*0.5f, y2b = y1 + v1*dt*0.5f;
    float v2a = v0 + k1a*dt*0.5f, v2b = v1 + k1b*dt*0.5f;
    float k2a, k2b; ACC(y2a, y2b, v2a, v2b, k2a, k2b);
    float y3a = y0 + v2a*dt*0.5f, y3b = y1 + v2b*dt*0.5f;
    float v3a = v0 + k2a*dt*0.5f, v3b = v1 + k2b*dt*0.5f;
    float k3a, k3b; ACC(y3a, y3b, v3a, v3b, k3a, k3b);
    float y4a = y0 + v3a*dt, y4b = y1 + v3b*dt;
    float v4a = v0 + k3a*dt, v4b = v1 + k3b*dt;
    float k4a, k4b; ACC(y4a, y4b, v4a, v4b, k4a, k4b);
    (void)y2a; (void)y2b; (void)y3a; (void)y3b; (void)y4a; (void)y4b;
    s[0] = y0 + dt/6.f * (v0 + 2.f*v2a + 2.f*v3a + v4a);
    s[1] = y1 + dt/6.f * (v1 + 2.f*v2b + 2.f*v3b + v4b);
    s[2] = v0 + dt/6.f * (k1a + 2.f*k2a + 2.f*k3a + k4a);
    s[3] = v1 + dt/6.f * (k1b + 2.f*k2b + 2.f*k3b + k4b);
#undef ACC
}

__device__ __forceinline__ void probe_AB(float* sA, float* sB,
                                         const float* M, const float* C,
                                         const float* K, const float* dtp, int t) {
    if (t < 4) {
        FSys m = mksys(M, C, K, dtp);
        float s[4] = {0.f, 0.f, 0.f, 0.f}; s[t] = 1.f;
        fstep(m, s, 0.f, 0.f);
        sA[0*4 + t] = s[0]; sA[1*4 + t] = s[1]; sA[2*4 + t] = s[2]; sA[3*4 + t] = s[3];
    } else if (t < 6) {
        FSys m = mksys(M, C, K, dtp);
        int j = t - 4;
        float s[4] = {0.f, 0.f, 0.f, 0.f};
        fstep(m, s, j == 0 ? 1.f : 0.f, j == 1 ? 1.f : 0.f);
        sB[0*2 + j] = s[0]; sB[1*2 + j] = s[1]; sB[2*2 + j] = s[2]; sB[3*2 + j] = s[3];
    }
}

// ---------------------------------------------------------------------------
// MATVEC4(Am, d..., x...): x <- Am * x + d   (d is the ADDITIVE term!)
// ---------------------------------------------------------------------------
#define MATVEC4(Am, d0, d1, d2, d3, x0_, x1_, x2_, x3_)                        \
    do {                                                                       \
        float n0 = fmaf((Am)[0],  (x0_), (Am)[1]  * (x1_)) +                   \
                   fmaf((Am)[2],  (x2_), fmaf((Am)[3],  (x3_), (d0)));         \
        float n1 = fmaf((Am)[4],  (x0_), (Am)[5]  * (x1_)) +                   \
                   fmaf((Am)[6],  (x2_), fmaf((Am)[7],  (x3_), (d1)));         \
        float n2 = fmaf((Am)[8],  (x0_), (Am)[9]  * (x1_)) +                   \
                   fmaf((Am)[10], (x2_), fmaf((Am)[11], (x3_), (d2)));         \
        float n3 = fmaf((Am)[12], (x0_), (Am)[13] * (x1_)) +                   \
                   fmaf((Am)[14], (x2_), fmaf((Am)[15], (x3_), (d3)));         \
        (x0_) = n0; (x1_) = n1; (x2_) = n2; (x3_) = n3;                        \
    } while (0)

// v <- Mat * v + b
#define AFFINE_F4(Mat, v, b)                                                   \
    do {                                                                       \
        float t0 = (v).x, t1 = (v).y, t2 = (v).z, t3 = (v).w;                  \
        MATVEC4(Mat, (b).x, (b).y, (b).z, (b).w, t0, t1, t2, t3);              \
        (v).x = t0; (v).y = t1; (v).z = t2; (v).w = t3;                        \
    } while (0)

// Cooperative 4x4 matmul (threads 0..15 of warp 0)
__device__ __forceinline__ void coop_mm(float* R, const float* Pm, const float* Qm, int t) {
    if (t < 16) {
        int i = t >> 2, j = t & 3;
        R[t] = fmaf(Pm[i*4+0], Qm[0*4+j],
               fmaf(Pm[i*4+1], Qm[1*4+j],
               fmaf(Pm[i*4+2], Qm[2*4+j],
                    Pm[i*4+3] * Qm[3*4+j])));
    }
    __syncwarp();
}

// ---------------------------------------------------------------------------
// Fused kernel
// ---------------------------------------------------------------------------
__global__ void __launch_bounds__(CPB, 1)
fused_kernel(const float4* __restrict__ u4, float4* __restrict__ out4,
             const float* __restrict__ M, const float* __restrict__ C,
             const float* __restrict__ K, const float* __restrict__ x0in,
             const float* __restrict__ dtp,
             int nf4, int nblocks) {
    __shared__ float sA[16], sB[8];
    __shared__ float sMp[5][16];      // M^1, M^2, M^4, M^8, M^16   (M = A^16)
    __shared__ float sM32[16];        // M^32
    __shared__ float sM64[16];        // M^64
    __shared__ float sTmp[16];
    __shared__ float sX0[4];          // initial state (reordered)
    __shared__ float4 s_w[2];         // warp totals
    __shared__ float4 s_Sw[2];        // warp start states
    __shared__ float4 s_bt[MAX_BLOCKS];
    __shared__ float2 s_u[L_CHUNK][CPB + 2];

    int tid = threadIdx.x;
    int lane = tid & 31;
    int wrp = tid >> 5;
    int c0 = blockIdx.x * CPB;

    probe_AB(sA, sB, M, C, K, dtp, tid);
    if (tid == 6) {   // x0 layout [y1,v1,y2,v2] -> state [y1,y2,v1,v2]
        sX0[0] = x0in[0]; sX0[1] = x0in[2]; sX0[2] = x0in[1]; sX0[3] = x0in[3];
    }

    // ---- stage u tile: 512 contiguous float4 -> transposed smem -------------
#pragma unroll
    for (int k = 0; k < 8; k++) {
        int idx = tid + CPB * k;
        int g4 = c0 * F4_PER_CHUNK + idx;
        float4 qv = (g4 < nf4) ? u4[g4] : make_float4(0.f, 0.f, 0.f, 0.f);
        int cc = idx >> 3, j = idx & 7;
        s_u[2*j][cc]     = make_float2(qv.x, qv.y);
        s_u[2*j + 1][cc] = make_float2(qv.z, qv.w);
    }
    __syncthreads();

    // ---- warp 0: build power table M^1..M^64 (M = A^16) ----------------------
    if (wrp == 0) {
        if (lane < 16) sTmp[lane] = sA[lane];
        __syncwarp();
        coop_mm(sMp[0], sTmp, sTmp, lane);               // A^2
        coop_mm(sTmp, sMp[0], sMp[0], lane);             // A^4
        coop_mm(sMp[0], sTmp, sTmp, lane);               // A^8
        coop_mm(sTmp, sMp[0], sMp[0], lane);             // A^16 = M^1
        if (lane < 16) sMp[0][lane] = sTmp[lane];
        __syncwarp();
        coop_mm(sMp[1], sMp[0], sMp[0], lane);           // M^2
        coop_mm(sMp[2], sMp[1], sMp[1], lane);           // M^4
        coop_mm(sMp[3], sMp[2], sMp[2], lane);           // M^8
        coop_mm(sMp[4], sMp[3], sMp[3], lane);           // M^16
        coop_mm(sM32,   sMp[4], sMp[4], lane);           // M^32
        coop_mm(sM64,   sM32,   sM32,   lane);           // M^64
    }

    float A[16], B[8];
#pragma unroll
    for (int i = 0; i < 16; i++) A[i] = sA[i];
#pragma unroll
    for (int i = 0; i < 8; i++) B[i] = sB[i];

    // ---- per-lane chunk drive (zero IC) --------------------------------------
    float d0 = 0.f, d1 = 0.f, d2 = 0.f, d3 = 0.f;
#pragma unroll
    for (int i = 0; i < L_CHUNK; i++) {
        float2 uu = s_u[i][tid];
        float w0 = fmaf(B[0], uu.x, B[1] * uu.y);
        float w1 = fmaf(B[2], uu.x, B[3] * uu.y);
        float w2 = fmaf(B[4], uu.x, B[5] * uu.y);
        float w3 = fmaf(B[6], uu.x, B[7] * uu.y);
        MATVEC4(A, w0, w1, w2, w3, d0, d1, d2, d3);
    }
    __syncthreads();   // power table ready for all warps

    // ---- warp Kogge-Stone inclusive affine scan over lanes -------------------
    float4 e = make_float4(d0, d1, d2, d3);
#pragma unroll
    for (int k = 0; k < 5; k++) {
        int off = 1 << k;
        float4 p;
        p.x = __shfl_up_sync(0xffffffffu, e.x, off);
        p.y = __shfl_up_sync(0xffffffffu, e.y, off);
        p.z = __shfl_up_sync(0xffffffffu, e.z, off);
        p.w = __shfl_up_sync(0xffffffffu, e.w, off);
        if (lane >= off) {
            float t0 = p.x, t1 = p.y, t2 = p.z, t3 = p.w;
            MATVEC4(sMp[k], e.x, e.y, e.z, e.w, t0, t1, t2, t3);  // t = M^2^k * p + e
            e = make_float4(t0, t1, t2, t3);
        }
    }
    if (lane == 31) s_w[wrp] = e;      // warp totals (inclusive drive, 32 chunks)
    __syncthreads();

    // ---- block total: E = M^32 * W0 + W1 -> g_bt ------------------------------
    if (tid == 0) {
        float4 bt = s_w[0];
        AFFINE_F4(sM32, bt, s_w[1]);
        g_bt[blockIdx.x] = bt;
    }

    grid_barrier(nblocks);   // the ONLY grid barrier

    // ---- every block: load all totals (L2 broadcast), fold OWN prefix --------
    for (int b = tid; b < nblocks; b += CPB)
        s_bt[b] = __ldcg(&g_bt[b]);
    __syncthreads();

    if (tid == 0) {
        float4 S = make_float4(sX0[0], sX0[1], sX0[2], sX0[3]);
        int myb = blockIdx.x;
        for (int b = 0; b < myb; b++) {
            float4 d = s_bt[b];
            AFFINE_F4(sM64, S, d);    // S = M^64 * S + E_b
        }
        // warp start states: Sw0 = S; Sw1 = M^32 * S + W0
        s_Sw[0] = S;
        float4 t = S;
        AFFINE_F4(sM32, t, s_w[0]);
        s_Sw[1] = t;
    }
    __syncthreads();

    // exclusive prefix of lane drives
    float4 eprev;
    eprev.x = __shfl_up_sync(0xffffffffu, e.x, 1);
    eprev.y = __shfl_up_sync(0xffffffffu, e.y, 1);
    eprev.z = __shfl_up_sync(0xffffffffu, e.z, 1);
    eprev.w = __shfl_up_sync(0xffffffffu, e.w, 1);
    if (lane == 0) eprev = make_float4(0.f, 0.f, 0.f, 0.f);

    // ladder: v <- M^(2^k) * v for each set bit of lane
    float4 v = s_Sw[wrp];
#pragma unroll
    for (int k = 0; k < 5; k++) {
        if ((lane >> k) & 1) {
            float t0 = v.x, t1 = v.y, t2 = v.z, t3 = v.w;
            MATVEC4(sMp[k], 0.f, 0.f, 0.f, 0.f, t0, t1, t2, t3);  // t = M^2^k * v
            v = make_float4(t0, t1, t2, t3);
        }
    }
    // this lane's chunk start state = M^lane * Sw + eprev
    float x0 = v.x + eprev.x, x1 = v.y + eprev.y;
    float x2 = v.z + eprev.z, x3 = v.w + eprev.w;

    // ---- replay 16 steps, write positions back into the tile -----------------
#pragma unroll
    for (int i = 0; i < L_CHUNK; i++) {
        float2 uu = s_u[i][tid];
        float w0 = fmaf(B[0], uu.x, B[1] * uu.y);
        float w1 = fmaf(B[2], uu.x, B[3] * uu.y);
        float w2 = fmaf(B[4], uu.x, B[5] * uu.y);
        float w3 = fmaf(B[6], uu.x, B[7] * uu.y);
        MATVEC4(A, w0, w1, w2, w3, x0, x1, x2, x3);
        s_u[i][tid] = make_float2(x0, x1);
    }
    __syncthreads();

    // ---- coalesced transposed store -------------------------------------------
#pragma unroll
    for (int k = 0; k < 8; k++) {
        int idx = tid + CPB * k;
        int g4 = c0 * F4_PER_CHUNK + idx;
        if (g4 < nf4) {
            int cc = idx >> 3, j = idx & 7;
            float2 a = s_u[2*j][cc];
            float2 b = s_u[2*j + 1][cc];
            out4[g4] = make_float4(a.x, a.y, b.x, b.y);
        }
    }
}

// ---------------------------------------------------------------------------
// Launch
// ---------------------------------------------------------------------------
extern "C" void kernel_launch(void* const* d_in, const int* in_sizes, int n_in,
                              void* d_out, int out_size) {
    const float* u  = (const float*)d_in[0];
    const float* M  = (const float*)d_in[1];
    const float* C  = (const float*)d_in[2];
    const float* K  = (const float*)d_in[3];
    const float* x0 = (const float*)d_in[4];
    const float* dt = (const float*)d_in[5];

    int T   = in_sizes[0] / 2;
    int NC  = (T + L_CHUNK - 1) / L_CHUNK;
    int nf4 = (2 * T) / 4;
    int nb  = (NC + CPB - 1) / CPB;   // 98 blocks for T=100000 — co-resident

    fused_kernel<<<nb, CPB>>>((const float4*)u, (float4*)d_out,
                              M, C, K, x0, dt, nf4, nb);
}

// round 11
// speedup vs baseline: 4.8722x; 1.0025x over previous
#include <cuda_runtime.h>
#include <cuda_bf16.h>

// Fused blocked affine-scan RK4 integrator, v8 (25 blocks x 256 threads;
// lighter barrier, shorter redundant prefix, pure-spin wake).
// x_{t+1} = A x_t + B u_t exactly. L=16 steps/chunk, 256 chunks/block.
//   per lane : 16-step chunk scan (smem tile, loaded once)
//   per warp : Kogge-Stone affine scan (M^(2^k) from smem power table)
//   per block: 8 warp totals -> block total E_b -> g_bt; ONE grid barrier;
//              every block folds its own prefix over <=24 E_*, rebuilds
//              warp/lane start states, replays, stores transposed.

#define L_CHUNK 16
#define CPB 256                     // chunks per block == threads per block
#define NWARP (CPB / 32)            // 8
#define F4_PER_CHUNK (L_CHUNK / 2)
#define MAX_BLOCKS 64

__device__ float4 g_bt[MAX_BLOCKS];        // per-block total drive
__device__ volatile unsigned g_sense = 0;  // monotonically increasing epoch
__device__ unsigned g_count = 0;           // arrival counter (self-resetting)

// ---------------------------------------------------------------------------
// Grid barrier: sense-reversing, pure L2 spin (no nanosleep)
// ---------------------------------------------------------------------------
__device__ __forceinline__ void grid_barrier(int nblocks) {
    __threadfence();
    __syncthreads();
    if (threadIdx.x == 0) {
        unsigned s = g_sense;
        unsigned my = atomicAdd(&g_count, 1);
        if (my == (unsigned)nblocks - 1) {
            g_count = 0;
            __threadfence();
            g_sense = s + 1;
        } else {
            while (g_sense == s) { }
        }
    }
    __syncthreads();
}

// ---------------------------------------------------------------------------
// fp32 RK4 step mirroring the reference arithmetic (basis probing only)
// ---------------------------------------------------------------------------
struct FSys { float Cm[4], Km[4], Md[2], dt; };

__device__ __forceinline__ FSys mksys(const float* M, const float* C,
                                      const float* K, const float* dtp) {
    FSys m;
    m.Md[0] = M[0]; m.Md[1] = M[1];
    float C0 = C[0], C1 = C[1], C2 = C[2];
    m.Cm[0] = C0 + C1; m.Cm[1] = -C1; m.Cm[2] = -C1; m.Cm[3] = C2 + C1;
    float K0 = K[0], K1 = K[1], K2 = K[2];
    m.Km[0] = K0 + K1; m.Km[1] = -K1; m.Km[2] = -K1; m.Km[3] = K2 + K1;
    m.dt = dtp[0];
    return m;
}

__device__ void fstep(const FSys& m, float s[4], float u0, float u1) {
    float dt = m.dt;
    float y0 = s[0], y1 = s[1], v0 = s[2], v1 = s[3];
#define ACC(z0, z1, w0, w1, a0, a1)                                             \
    a0 = (u0 - (m.Cm[0]*(w0) + m.Cm[1]*(w1)) - (m.Km[0]*(z0) + m.Km[1]*(z1))) / m.Md[0]; \
    a1 = (u1 - (m.Cm[2]*(w0) + m.Cm[3]*(w1)) - (m.Km[2]*(z0) + m.Km[3]*(z1))) / m.Md[1];
    float k1a, k1b; ACC(y0, y1, v0, v1, k1a, k1b);
    float y2a = y0 + v0*dt*0.5f, y2b = y1 + v1*dt*0.5f;
    float v2a = v0 + k1a*dt*0.5f, v2b = v1 + k1b*dt*0.5f;
    float k2a, k2b; ACC(y2a, y2b, v2a, v2b, k2a, k2b);
    float y3a = y0 + v2a*dt*0.5f, y3b = y1 + v2b*dt*0.5f;
    float v3a = v0 + k2a*dt*0.5f, v3b = v1 + k2b*dt*0.5f;
    float k3a, k3b; ACC(y3a, y3b, v3a, v3b, k3a, k3b);
    float y4a = y0 + v3a*dt, y4b = y1 + v3b*dt;
    float v4a = v0 + k3a*dt, v4b = v1 + k3b*dt;
    float k4a, k4b; ACC(y4a, y4b, v4a, v4b, k4a, k4b);
    (void)y2a; (void)y2b; (void)y3a; (void)y3b; (void)y4a; (void)y4b;
    s[0] = y0 + dt/6.f * (v0 + 2.f*v2a + 2.f*v3a + v4a);
    s[1] = y1 + dt/6.f * (v1 + 2.f*v2b + 2.f*v3b + v4b);
    s[2] = v0 + dt/6.f * (k1a + 2.f*k2a + 2.f*k3a + k4a);
    s[3] = v1 + dt/6.f * (k1b + 2.f*k2b + 2.f*k3b + k4b);
#undef ACC
}

__device__ __forceinline__ void probe_AB(float* sA, float* sB,
                                         const float* M, const float* C,
                                         const float* K, const float* dtp, int t) {
    if (t < 4) {
        FSys m = mksys(M, C, K, dtp);
        float s[4] = {0.f, 0.f, 0.f, 0.f}; s[t] = 1.f;
        fstep(m, s, 0.f, 0.f);
        sA[0*4 + t] = s[0]; sA[1*4 + t] = s[1]; sA[2*4 + t] = s[2]; sA[3*4 + t] = s[3];
    } else if (t < 6) {
        FSys m = mksys(M, C, K, dtp);
        int j = t - 4;
        float s[4] = {0.f, 0.f, 0.f, 0.f};
        fstep(m, s, j == 0 ? 1.f : 0.f, j == 1 ? 1.f : 0.f);
        sB[0*2 + j] = s[0]; sB[1*2 + j] = s[1]; sB[2*2 + j] = s[2]; sB[3*2 + j] = s[3];
    }
}

// ---------------------------------------------------------------------------
// MATVEC4(Am, d..., x...): x <- Am * x + d   (d is the ADDITIVE term!)
// ---------------------------------------------------------------------------
#define MATVEC4(Am, d0, d1, d2, d3, x0_, x1_, x2_, x3_)                        \
    do {                                                                       \
        float n0 = fmaf((Am)[0],  (x0_), (Am)[1]  * (x1_)) +                   \
                   fmaf((Am)[2],  (x2_), fmaf((Am)[3],  (x3_), (d0)));         \
        float n1 = fmaf((Am)[4],  (x0_), (Am)[5]  * (x1_)) +                   \
                   fmaf((Am)[6],  (x2_), fmaf((Am)[7],  (x3_), (d1)));         \
        float n2 = fmaf((Am)[8],  (x0_), (Am)[9]  * (x1_)) +                   \
                   fmaf((Am)[10], (x2_), fmaf((Am)[11], (x3_), (d2)));         \
        float n3 = fmaf((Am)[12], (x0_), (Am)[13] * (x1_)) +                   \
                   fmaf((Am)[14], (x2_), fmaf((Am)[15], (x3_), (d3)));         \
        (x0_) = n0; (x1_) = n1; (x2_) = n2; (x3_) = n3;                        \
    } while (0)

// v <- Mat * v + b
#define AFFINE_F4(Mat, v, b)                                                   \
    do {                                                                       \
        float t0 = (v).x, t1 = (v).y, t2 = (v).z, t3 = (v).w;                  \
        MATVEC4(Mat, (b).x, (b).y, (b).z, (b).w, t0, t1, t2, t3);              \
        (v).x = t0; (v).y = t1; (v).z = t2; (v).w = t3;                        \
    } while (0)

// Cooperative 4x4 matmul (threads 0..15 of warp 0)
__device__ __forceinline__ void coop_mm(float* R, const float* Pm, const float* Qm, int t) {
    if (t < 16) {
        int i = t >> 2, j = t & 3;
        R[t] = fmaf(Pm[i*4+0], Qm[0*4+j],
               fmaf(Pm[i*4+1], Qm[1*4+j],
               fmaf(Pm[i*4+2], Qm[2*4+j],
                    Pm[i*4+3] * Qm[3*4+j])));
    }
    __syncwarp();
}

// ---------------------------------------------------------------------------
// Fused kernel
// ---------------------------------------------------------------------------
__global__ void __launch_bounds__(CPB, 1)
fused_kernel(const float4* __restrict__ u4, float4* __restrict__ out4,
             const float* __restrict__ M, const float* __restrict__ C,
             const float* __restrict__ K, const float* __restrict__ x0in,
             const float* __restrict__ dtp,
             int nf4, int nblocks) {
    __shared__ float sA[16], sB[8];
    __shared__ float sMp[5][16];      // M^1..M^16  (M = A^16)
    __shared__ float sM32[16];        // M^32 (warp stride)
    __shared__ float sM256[16];       // M^256 (block stride)
    __shared__ float sT1[16], sT2[16];
    __shared__ float sX0[4];
    __shared__ float4 s_w[NWARP];     // warp totals
    __shared__ float4 s_Sw[NWARP];    // warp start states
    __shared__ float4 s_bt[MAX_BLOCKS];
    __shared__ float2 s_u[L_CHUNK][CPB + 2];

    int tid = threadIdx.x;
    int lane = tid & 31;
    int wrp = tid >> 5;
    int c0 = blockIdx.x * CPB;

    probe_AB(sA, sB, M, C, K, dtp, tid);
    if (tid == 6) {   // x0 layout [y1,v1,y2,v2] -> state [y1,y2,v1,v2]
        sX0[0] = x0in[0]; sX0[1] = x0in[2]; sX0[2] = x0in[1]; sX0[3] = x0in[3];
    }

    // ---- stage u tile: 2048 contiguous float4 -> transposed smem -------------
#pragma unroll
    for (int k = 0; k < 8; k++) {
        int idx = tid + CPB * k;
        int g4 = c0 * F4_PER_CHUNK + idx;
        float4 qv = (g4 < nf4) ? u4[g4] : make_float4(0.f, 0.f, 0.f, 0.f);
        int cc = idx >> 3, j = idx & 7;
        s_u[2*j][cc]     = make_float2(qv.x, qv.y);
        s_u[2*j + 1][cc] = make_float2(qv.z, qv.w);
    }
    __syncthreads();

    // ---- warp 0: power table M^1..M^16, M^32, M^256 ---------------------------
    if (wrp == 0) {
        if (lane < 16) sT1[lane] = sA[lane];
        __syncwarp();
        coop_mm(sT2, sT1, sT1, lane);                    // A^2
        coop_mm(sT1, sT2, sT2, lane);                    // A^4
        coop_mm(sT2, sT1, sT1, lane);                    // A^8
        coop_mm(sMp[0], sT2, sT2, lane);                 // A^16 = M
        coop_mm(sMp[1], sMp[0], sMp[0], lane);           // M^2
        coop_mm(sMp[2], sMp[1], sMp[1], lane);           // M^4
        coop_mm(sMp[3], sMp[2], sMp[2], lane);           // M^8
        coop_mm(sMp[4], sMp[3], sMp[3], lane);           // M^16
        coop_mm(sM32,   sMp[4], sMp[4], lane);           // M^32
        coop_mm(sT1,    sM32,   sM32,   lane);           // M^64
        coop_mm(sT2,    sT1,    sT1,    lane);           // M^128
        coop_mm(sM256,  sT2,    sT2,    lane);           // M^256
    }

    float A[16], B[8];
#pragma unroll
    for (int i = 0; i < 16; i++) A[i] = sA[i];
#pragma unroll
    for (int i = 0; i < 8; i++) B[i] = sB[i];

    // ---- per-lane chunk drive (zero IC) --------------------------------------
    float d0 = 0.f, d1 = 0.f, d2 = 0.f, d3 = 0.f;
#pragma unroll
    for (int i = 0; i < L_CHUNK; i++) {
        float2 uu = s_u[i][tid];
        float w0 = fmaf(B[0], uu.x, B[1] * uu.y);
        float w1 = fmaf(B[2], uu.x, B[3] * uu.y);
        float w2 = fmaf(B[4], uu.x, B[5] * uu.y);
        float w3 = fmaf(B[6], uu.x, B[7] * uu.y);
        MATVEC4(A, w0, w1, w2, w3, d0, d1, d2, d3);
    }
    __syncthreads();   // power table ready for all warps

    // ---- warp Kogge-Stone inclusive affine scan over lanes -------------------
    float4 e = make_float4(d0, d1, d2, d3);
#pragma unroll
    for (int k = 0; k < 5; k++) {
        int off = 1 << k;
        float4 p;
        p.x = __shfl_up_sync(0xffffffffu, e.x, off);
        p.y = __shfl_up_sync(0xffffffffu, e.y, off);
        p.z = __shfl_up_sync(0xffffffffu, e.z, off);
        p.w = __shfl_up_sync(0xffffffffu, e.w, off);
        if (lane >= off) {
            float t0 = p.x, t1 = p.y, t2 = p.z, t3 = p.w;
            MATVEC4(sMp[k], e.x, e.y, e.z, e.w, t0, t1, t2, t3);  // t = M^2^k * p + e
            e = make_float4(t0, t1, t2, t3);
        }
    }
    if (lane == 31) s_w[wrp] = e;      // warp totals (inclusive, 32 chunks each)
    __syncthreads();

    // ---- block total: E = fold(M^32, W0..W7) -> g_bt ---------------------------
    if (tid == 0) {
        float4 bt = s_w[0];
#pragma unroll
        for (int w = 1; w < NWARP; w++)
            AFFINE_F4(sM32, bt, s_w[w]);   // bt = M^32 * bt + W_w
        g_bt[blockIdx.x] = bt;
    }

    grid_barrier(nblocks);   // the ONLY grid barrier

    // ---- every block: load all totals (L2 broadcast), fold OWN prefix --------
    if (tid < nblocks) s_bt[tid] = __ldcg(&g_bt[tid]);
    __syncthreads();

    if (tid == 0) {
        float4 S = make_float4(sX0[0], sX0[1], sX0[2], sX0[3]);
        int myb = blockIdx.x;
        for (int b = 0; b < myb; b++) {
            float4 d = s_bt[b];
            AFFINE_F4(sM256, S, d);    // S = M^256 * S + E_b
        }
        // warp start states: Sw_w = M^32 * Sw_{w-1} + W_{w-1}
#pragma unroll
        for (int w = 0; w < NWARP; w++) {
            s_Sw[w] = S;
            AFFINE_F4(sM32, S, s_w[w]);
        }
    }
    __syncthreads();

    // exclusive prefix of lane drives
    float4 eprev;
    eprev.x = __shfl_up_sync(0xffffffffu, e.x, 1);
    eprev.y = __shfl_up_sync(0xffffffffu, e.y, 1);
    eprev.z = __shfl_up_sync(0xffffffffu, e.z, 1);
    eprev.w = __shfl_up_sync(0xffffffffu, e.w, 1);
    if (lane == 0) eprev = make_float4(0.f, 0.f, 0.f, 0.f);

    // ladder: v <- M^(2^k) * v for each set bit of lane
    float4 v = s_Sw[wrp];
#pragma unroll
    for (int k = 0; k < 5; k++) {
        if ((lane >> k) & 1) {
            float t0 = v.x, t1 = v.y, t2 = v.z, t3 = v.w;
            MATVEC4(sMp[k], 0.f, 0.f, 0.f, 0.f, t0, t1, t2, t3);  // t = M^2^k * v
            v = make_float4(t0, t1, t2, t3);
        }
    }
    // this lane's chunk start state = M^lane * Sw + eprev
    float x0 = v.x + eprev.x, x1 = v.y + eprev.y;
    float x2 = v.z + eprev.z, x3 = v.w + eprev.w;

    // ---- replay 16 steps, write positions back into the tile -----------------
#pragma unroll
    for (int i = 0; i < L_CHUNK; i++) {
        float2 uu = s_u[i][tid];
        float w0 = fmaf(B[0], uu.x, B[1] * uu.y);
        float w1 = fmaf(B[2], uu.x, B[3] * uu.y);
        float w2 = fmaf(B[4], uu.x, B[5] * uu.y);
        float w3 = fmaf(B[6], uu.x, B[7] * uu.y);
        MATVEC4(A, w0, w1, w2, w3, x0, x1, x2, x3);
        s_u[i][tid] = make_float2(x0, x1);
    }
    __syncthreads();

    // ---- coalesced transposed store -------------------------------------------
#pragma unroll
    for (int k = 0; k < 8; k++) {
        int idx = tid + CPB * k;
        int g4 = c0 * F4_PER_CHUNK + idx;
        if (g4 < nf4) {
            int cc = idx >> 3, j = idx & 7;
            float2 a = s_u[2*j][cc];
            float2 b = s_u[2*j + 1][cc];
            out4[g4] = make_float4(a.x, a.y, b.x, b.y);
        }
    }
}

// ---------------------------------------------------------------------------
// Launch
// ---------------------------------------------------------------------------
extern "C" void kernel_launch(void* const* d_in, const int* in_sizes, int n_in,
                              void* d_out, int out_size) {
    const float* u  = (const float*)d_in[0];
    const float* M  = (const float*)d_in[1];
    const float* C  = (const float*)d_in[2];
    const float* K  = (const float*)d_in[3];
    const float* x0 = (const float*)d_in[4];
    const float* dt = (const float*)d_in[5];

    int T   = in_sizes[0] / 2;
    int NC  = (T + L_CHUNK - 1) / L_CHUNK;
    int nf4 = (2 * T) / 4;
    int nb  = (NC + CPB - 1) / CPB;   // 25 blocks for T=100000 — co-resident

    fused_kernel<<<nb, CPB>>>((const float4*)u, (float4*)d_out,
                              M, C, K, x0, dt, nf4, nb);
}